// round 1
// baseline (speedup 1.0000x reference)
#include <cuda_runtime.h>
#include <float.h>

#define N_NODES 50000
#define DEG     32
#define WID     128
#define BATCH   4096
#define AS_LD   132          // padded A stride (floats) to soften LDS bank conflicts
#define NTHREADS 256

// ---------------- device scratch (no allocations allowed) ----------------
__device__ int   g_winner[N_NODES];          // last batch slot writing each node, else -1
__device__ float g_Mb[BATCH * WID];          // relu(feats @ Wa^T + ba)
__device__ float g_Fh[BATCH * WID];          // feats @ Wlh^T   (no bias/relu)
__device__ float g_H1[N_NODES * WID];        // layer-1 output (normalized)
__device__ float g_M2[N_NODES * WID];        // relu(H1 @ Wa^T + ba)
__device__ float g_WaT[WID * WID];           // k-major transposed weights
__device__ float g_WlhT[WID * WID];
__device__ float g_WlaT[WID * WID];

typedef unsigned long long u64;

__device__ __forceinline__ u64 f2pack(float lo, float hi) {
    u64 r; asm("mov.b64 %0, {%1, %2};" : "=l"(r) : "f"(lo), "f"(hi)); return r;
}
__device__ __forceinline__ void f2unpack(u64 v, float& lo, float& hi) {
    asm("mov.b64 {%0, %1}, %2;" : "=f"(lo), "=f"(hi) : "l"(v));
}
__device__ __forceinline__ void f2fma(u64& c, u64 a, u64 b) {
    asm("fma.rn.f32x2 %0, %1, %2, %0;" : "+l"(c) : "l"(a), "l"(b));
}

// ---------------- 128x128x128 tile GEMM, fp32x2 packed FMA ----------------
// As: [128][AS_LD] row(node)-major.  Wt: [128][128] k-major (row k holds all 128 out dims).
// 256 threads; thread (tx = tid&7, ty = tid>>3) owns rows ty*4+i (i<4), cols tx*16..tx*16+15.
__device__ __forceinline__ void gemm128(const float* __restrict__ As,
                                        const float* __restrict__ Wt,
                                        u64 C[4][8], int tx, int ty) {
#pragma unroll 4
    for (int k = 0; k < WID; ++k) {
        const ulonglong2* bp = (const ulonglong2*)(Wt + k * WID + tx * 16);
        ulonglong2 b01 = bp[0], b23 = bp[1], b45 = bp[2], b67 = bp[3];
        u64 bb[8] = { b01.x, b01.y, b23.x, b23.y, b45.x, b45.y, b67.x, b67.y };
#pragma unroll
        for (int i = 0; i < 4; ++i) {
            float a = As[(ty * 4 + i) * AS_LD + k];
            u64 aa = f2pack(a, a);
#pragma unroll
            for (int j = 0; j < 8; ++j) f2fma(C[i][j], aa, bb[j]);
        }
    }
}

__device__ __forceinline__ void zeroC(u64 C[4][8]) {
#pragma unroll
    for (int i = 0; i < 4; ++i)
#pragma unroll
        for (int j = 0; j < 8; ++j) C[i][j] = 0ull;
}

__device__ __forceinline__ void load_weights(float* Wt, const float* __restrict__ src) {
    for (int e = threadIdx.x; e < WID * WID / 4; e += NTHREADS)
        *(float4*)(Wt + e * 4) = *(const float4*)(src + e * 4);
}

// ---------------- small setup kernels ----------------
__global__ void k_init(const float* __restrict__ W_agg, const float* __restrict__ W_lin) {
    int t = blockIdx.x * NTHREADS + threadIdx.x;
    if (t < N_NODES) g_winner[t] = -1;
    if (t < WID * WID) {
        int k = t >> 7, d = t & 127;
        g_WaT[t]  = W_agg[d * WID + k];
        g_WlhT[t] = W_lin[d * (2 * WID) + k];
        g_WlaT[t] = W_lin[d * (2 * WID) + WID + k];
    }
}

__global__ void k_scatter(const int* __restrict__ node_idx) {
    int i = blockIdx.x * NTHREADS + threadIdx.x;
    if (i < BATCH) atomicMax(&g_winner[node_idx[i]], i);
}

// ---------------- batch precompute: Mb and Fh (two GEMM passes) ----------------
__global__ void __launch_bounds__(NTHREADS, 1)
k_batch(const float* __restrict__ feats, const float* __restrict__ b_agg) {
    extern __shared__ float sm[];
    float* As = sm;
    float* Wt = sm + WID * AS_LD;
    const int tid = threadIdx.x;
    const int tx = tid & 7, ty = tid >> 3;
    const int r0 = blockIdx.x * WID;

    for (int e = tid; e < WID * WID / 4; e += NTHREADS) {
        int row = e >> 5, c4 = (e & 31) << 2;
        *(float4*)(As + row * AS_LD + c4) = *(const float4*)(feats + (r0 + row) * WID + c4);
    }
    load_weights(Wt, g_WaT);
    __syncthreads();

    u64 C[4][8];
    zeroC(C);
    gemm128(As, Wt, C, tx, ty);

    float bav[16];
#pragma unroll
    for (int q = 0; q < 4; ++q) {
        float4 b = *(const float4*)(b_agg + tx * 16 + q * 4);
        bav[q * 4 + 0] = b.x; bav[q * 4 + 1] = b.y; bav[q * 4 + 2] = b.z; bav[q * 4 + 3] = b.w;
    }
#pragma unroll
    for (int i = 0; i < 4; ++i) {
        int row = ty * 4 + i;
        float v[16];
#pragma unroll
        for (int j = 0; j < 8; ++j) f2unpack(C[i][j], v[2 * j], v[2 * j + 1]);
        float* dst = g_Mb + (r0 + row) * WID + tx * 16;
#pragma unroll
        for (int q = 0; q < 4; ++q) {
            float4 o;
            o.x = fmaxf(v[q * 4 + 0] + bav[q * 4 + 0], 0.f);
            o.y = fmaxf(v[q * 4 + 1] + bav[q * 4 + 1], 0.f);
            o.z = fmaxf(v[q * 4 + 2] + bav[q * 4 + 2], 0.f);
            o.w = fmaxf(v[q * 4 + 3] + bav[q * 4 + 3], 0.f);
            *(float4*)(dst + q * 4) = o;
        }
    }
    __syncthreads();                 // gemm readers of Wt done
    load_weights(Wt, g_WlhT);
    __syncthreads();

    zeroC(C);
    gemm128(As, Wt, C, tx, ty);
#pragma unroll
    for (int i = 0; i < 4; ++i) {
        int row = ty * 4 + i;
        float v[16];
#pragma unroll
        for (int j = 0; j < 8; ++j) f2unpack(C[i][j], v[2 * j], v[2 * j + 1]);
        float* dst = g_Fh + (r0 + row) * WID + tx * 16;
#pragma unroll
        for (int q = 0; q < 4; ++q)
            *(float4*)(dst + q * 4) = make_float4(v[q * 4], v[q * 4 + 1], v[q * 4 + 2], v[q * 4 + 3]);
    }
}

// ---------------- layer 1 fused: sparse agg + combine GEMM + relu + l2norm ----------------
__global__ void __launch_bounds__(NTHREADS, 1)
k_layer1(const int* __restrict__ nbd, const float* __restrict__ b_agg,
         const float* __restrict__ b_lin) {
    extern __shared__ float sm[];
    float* As = sm;                       // agg tile, then reused as output staging
    float* Wt = sm + WID * AS_LD;
    float* rn = Wt + WID * WID;
    const int tid = threadIdx.x;
    const int lane = tid & 31, warp = tid >> 5;
    const int tx = tid & 7, ty = tid >> 3;
    const int r0 = blockIdx.x * WID;

    // c = relu(b_agg), the M1 row of every non-batch node
    float4 bag = *(const float4*)(b_agg + lane * 4);
    float4 cvec = make_float4(fmaxf(bag.x, 0.f), fmaxf(bag.y, 0.f),
                              fmaxf(bag.z, 0.f), fmaxf(bag.w, 0.f));

    // phase A: aggregate (warp per node, lane owns dims lane*4..lane*4+3)
#pragma unroll 1
    for (int p = 0; p < 16; ++p) {
        int n = warp + p * 8;
        int gn = r0 + n;                  // warp-uniform
        float4 acc;
        if (gn < N_NODES) {
            int nb = nbd[gn * DEG + lane];
            int wv = g_winner[nb];
            acc = make_float4(-FLT_MAX, -FLT_MAX, -FLT_MAX, -FLT_MAX);
            int hasPlain = 0;
#pragma unroll 1
            for (int j = 0; j < DEG; ++j) {
                int wj = __shfl_sync(0xffffffffu, wv, j);
                if (wj >= 0) {
                    float4 m = *(const float4*)(g_Mb + wj * WID + lane * 4);
                    acc.x = fmaxf(acc.x, m.x); acc.y = fmaxf(acc.y, m.y);
                    acc.z = fmaxf(acc.z, m.z); acc.w = fmaxf(acc.w, m.w);
                } else hasPlain = 1;
            }
            if (hasPlain) {
                acc.x = fmaxf(acc.x, cvec.x); acc.y = fmaxf(acc.y, cvec.y);
                acc.z = fmaxf(acc.z, cvec.z); acc.w = fmaxf(acc.w, cvec.w);
            }
        } else {
            acc = make_float4(0.f, 0.f, 0.f, 0.f);
        }
        *(float4*)(As + n * AS_LD + lane * 4) = acc;
    }
    load_weights(Wt, g_WlaT);
    __syncthreads();

    u64 C[4][8];
    zeroC(C);
    gemm128(As, Wt, C, tx, ty);
    __syncthreads();                      // done reading As, can restage

    float blv[16];
#pragma unroll
    for (int q = 0; q < 4; ++q) {
        float4 b = *(const float4*)(b_lin + tx * 16 + q * 4);
        blv[q * 4 + 0] = b.x; blv[q * 4 + 1] = b.y; blv[q * 4 + 2] = b.z; blv[q * 4 + 3] = b.w;
    }
#pragma unroll
    for (int i = 0; i < 4; ++i) {
        int row = ty * 4 + i, gn = r0 + row;
        float v[16];
#pragma unroll
        for (int j = 0; j < 8; ++j) f2unpack(C[i][j], v[2 * j], v[2 * j + 1]);
#pragma unroll
        for (int c = 0; c < 16; ++c) v[c] += blv[c];
        if (gn < N_NODES) {
            int w = g_winner[gn];
            if (w >= 0) {                 // H0 contribution: feats[w] @ Wlh^T
                const float* fh = g_Fh + w * WID + tx * 16;
#pragma unroll
                for (int q = 0; q < 4; ++q) {
                    float4 f = *(const float4*)(fh + q * 4);
                    v[q * 4 + 0] += f.x; v[q * 4 + 1] += f.y;
                    v[q * 4 + 2] += f.z; v[q * 4 + 3] += f.w;
                }
            }
        }
#pragma unroll
        for (int c = 0; c < 16; ++c) v[c] = fmaxf(v[c], 0.f);
#pragma unroll
        for (int q = 0; q < 4; ++q)
            *(float4*)(As + row * AS_LD + tx * 16 + q * 4) =
                make_float4(v[q * 4], v[q * 4 + 1], v[q * 4 + 2], v[q * 4 + 3]);
    }
    __syncthreads();

    if (tid < WID) {
        float s = 0.f;
        const float* rowp = As + tid * AS_LD;
#pragma unroll
        for (int k4 = 0; k4 < WID; k4 += 4) {
            float4 u = *(const float4*)(rowp + k4);
            s += u.x * u.x + u.y * u.y + u.z * u.z + u.w * u.w;
        }
        rn[tid] = 1.0f / fmaxf(sqrtf(s), 1e-12f);
    }
    __syncthreads();

    for (int e = tid; e < WID * WID / 4; e += NTHREADS) {
        int row = e >> 5, c4 = (e & 31) << 2;
        int gn = r0 + row;
        if (gn < N_NODES) {
            float s = rn[row];
            float4 u = *(const float4*)(As + row * AS_LD + c4);
            u.x *= s; u.y *= s; u.z *= s; u.w *= s;
            *(float4*)(g_H1 + gn * WID + c4) = u;
        }
    }
}

// ---------------- layer 2: M2 = relu(H1 @ Wa^T + ba) ----------------
__global__ void __launch_bounds__(NTHREADS, 1)
k_l2m(const float* __restrict__ b_agg) {
    extern __shared__ float sm[];
    float* As = sm;
    float* Wt = sm + WID * AS_LD;
    const int tid = threadIdx.x;
    const int tx = tid & 7, ty = tid >> 3;
    const int r0 = blockIdx.x * WID;

    for (int e = tid; e < WID * WID / 4; e += NTHREADS) {
        int row = e >> 5, c4 = (e & 31) << 2;
        int gn = r0 + row;
        float4 v = (gn < N_NODES) ? *(const float4*)(g_H1 + gn * WID + c4)
                                  : make_float4(0.f, 0.f, 0.f, 0.f);
        *(float4*)(As + row * AS_LD + c4) = v;
    }
    load_weights(Wt, g_WaT);
    __syncthreads();

    u64 C[4][8];
    zeroC(C);
    gemm128(As, Wt, C, tx, ty);

    float bav[16];
#pragma unroll
    for (int q = 0; q < 4; ++q) {
        float4 b = *(const float4*)(b_agg + tx * 16 + q * 4);
        bav[q * 4 + 0] = b.x; bav[q * 4 + 1] = b.y; bav[q * 4 + 2] = b.z; bav[q * 4 + 3] = b.w;
    }
#pragma unroll
    for (int i = 0; i < 4; ++i) {
        int row = ty * 4 + i, gn = r0 + row;
        if (gn >= N_NODES) continue;
        float v[16];
#pragma unroll
        for (int j = 0; j < 8; ++j) f2unpack(C[i][j], v[2 * j], v[2 * j + 1]);
        float* dst = g_M2 + gn * WID + tx * 16;
#pragma unroll
        for (int q = 0; q < 4; ++q) {
            float4 o;
            o.x = fmaxf(v[q * 4 + 0] + bav[q * 4 + 0], 0.f);
            o.y = fmaxf(v[q * 4 + 1] + bav[q * 4 + 1], 0.f);
            o.z = fmaxf(v[q * 4 + 2] + bav[q * 4 + 2], 0.f);
            o.w = fmaxf(v[q * 4 + 3] + bav[q * 4 + 3], 0.f);
            *(float4*)(dst + q * 4) = o;
        }
    }
}

// ---------------- layer 2 final: batch-only agg + 256-K combine + norm ----------------
__global__ void __launch_bounds__(NTHREADS, 1)
k_l2f(const int* __restrict__ nbd, const int* __restrict__ node_idx,
      const float* __restrict__ b_lin, float* __restrict__ out) {
    extern __shared__ float sm[];
    float* A1 = sm;                       // H1 rows of the batch nodes; later output staging
    float* A2 = A1 + WID * AS_LD;         // agg2 rows
    float* Wt = A2 + WID * AS_LD;
    float* rn = Wt + WID * WID;
    int*   nid = (int*)(rn + WID);
    const int tid = threadIdx.x;
    const int lane = tid & 31, warp = tid >> 5;
    const int tx = tid & 7, ty = tid >> 3;
    const int r0 = blockIdx.x * WID;

    if (tid < WID) nid[tid] = node_idx[r0 + tid];
    __syncthreads();

    for (int e = tid; e < WID * WID / 4; e += NTHREADS) {
        int row = e >> 5, c4 = (e & 31) << 2;
        *(float4*)(A1 + row * AS_LD + c4) = *(const float4*)(g_H1 + nid[row] * WID + c4);
    }
#pragma unroll 1
    for (int p = 0; p < 16; ++p) {
        int n = warp + p * 8;
        int gn = nid[n];                  // warp-uniform shared read
        int nb = nbd[gn * DEG + lane];
        float4 acc = make_float4(-FLT_MAX, -FLT_MAX, -FLT_MAX, -FLT_MAX);
#pragma unroll 1
        for (int j = 0; j < DEG; ++j) {
            int nbj = __shfl_sync(0xffffffffu, nb, j);
            float4 m = *(const float4*)(g_M2 + nbj * WID + lane * 4);
            acc.x = fmaxf(acc.x, m.x); acc.y = fmaxf(acc.y, m.y);
            acc.z = fmaxf(acc.z, m.z); acc.w = fmaxf(acc.w, m.w);
        }
        *(float4*)(A2 + n * AS_LD + lane * 4) = acc;
    }
    load_weights(Wt, g_WlhT);
    __syncthreads();

    u64 C[4][8];
    zeroC(C);
    gemm128(A1, Wt, C, tx, ty);
    __syncthreads();
    load_weights(Wt, g_WlaT);
    __syncthreads();
    gemm128(A2, Wt, C, tx, ty);           // accumulate second K-half
    __syncthreads();                      // done reading A1/A2

    float blv[16];
#pragma unroll
    for (int q = 0; q < 4; ++q) {
        float4 b = *(const float4*)(b_lin + tx * 16 + q * 4);
        blv[q * 4 + 0] = b.x; blv[q * 4 + 1] = b.y; blv[q * 4 + 2] = b.z; blv[q * 4 + 3] = b.w;
    }
#pragma unroll
    for (int i = 0; i < 4; ++i) {
        int row = ty * 4 + i;
        float v[16];
#pragma unroll
        for (int j = 0; j < 8; ++j) f2unpack(C[i][j], v[2 * j], v[2 * j + 1]);
#pragma unroll
        for (int c = 0; c < 16; ++c) v[c] = fmaxf(v[c] + blv[c], 0.f);
#pragma unroll
        for (int q = 0; q < 4; ++q)
            *(float4*)(A1 + row * AS_LD + tx * 16 + q * 4) =
                make_float4(v[q * 4], v[q * 4 + 1], v[q * 4 + 2], v[q * 4 + 3]);
    }
    __syncthreads();

    if (tid < WID) {
        float s = 0.f;
        const float* rowp = A1 + tid * AS_LD;
#pragma unroll
        for (int k4 = 0; k4 < WID; k4 += 4) {
            float4 u = *(const float4*)(rowp + k4);
            s += u.x * u.x + u.y * u.y + u.z * u.z + u.w * u.w;
        }
        rn[tid] = 1.0f / fmaxf(sqrtf(s), 1e-12f);
    }
    __syncthreads();

    for (int e = tid; e < WID * WID / 4; e += NTHREADS) {
        int row = e >> 5, c4 = (e & 31) << 2;
        float s = rn[row];
        float4 u = *(const float4*)(A1 + row * AS_LD + c4);
        u.x *= s; u.y *= s; u.z *= s; u.w *= s;
        *(float4*)(out + (r0 + row) * WID + c4) = u;
    }
}

// ---------------- launch ----------------
extern "C" void kernel_launch(void* const* d_in, const int* in_sizes, int n_in,
                              void* d_out, int out_size) {
    const int*   nbd      = (const int*)d_in[0];
    const int*   node_idx = (const int*)d_in[1];
    const float* feats    = (const float*)d_in[2];
    const float* W_agg    = (const float*)d_in[3];
    const float* b_agg    = (const float*)d_in[4];
    const float* W_lin    = (const float*)d_in[5];
    const float* b_lin    = (const float*)d_in[6];
    float* out = (float*)d_out;

    const int smAW  = (WID * AS_LD + WID * WID) * (int)sizeof(float);                 // 133120
    const int smL1  = smAW + WID * (int)sizeof(float);                                // +rn
    const int smL2F = (2 * WID * AS_LD + WID * WID + WID) * (int)sizeof(float)
                      + WID * (int)sizeof(int);                                       // 201728

    cudaFuncSetAttribute(k_batch,  cudaFuncAttributeMaxDynamicSharedMemorySize, smAW);
    cudaFuncSetAttribute(k_layer1, cudaFuncAttributeMaxDynamicSharedMemorySize, smL1);
    cudaFuncSetAttribute(k_l2m,    cudaFuncAttributeMaxDynamicSharedMemorySize, smAW);
    cudaFuncSetAttribute(k_l2f,    cudaFuncAttributeMaxDynamicSharedMemorySize, smL2F);

    k_init<<<(N_NODES + NTHREADS - 1) / NTHREADS, NTHREADS>>>(W_agg, W_lin);
    k_scatter<<<BATCH / NTHREADS, NTHREADS>>>(node_idx);
    k_batch<<<BATCH / WID, NTHREADS, smAW>>>(feats, b_agg);
    k_layer1<<<(N_NODES + WID - 1) / WID, NTHREADS, smL1>>>(nbd, b_agg, b_lin);
    k_l2m<<<(N_NODES + WID - 1) / WID, NTHREADS, smAW>>>(b_agg);
    k_l2f<<<BATCH / WID, NTHREADS, smL2F>>>(nbd, node_idx, b_lin, out);
}